// round 4
// baseline (speedup 1.0000x reference)
#include <cuda_runtime.h>
#include <cuda_bf16.h>

// PLIF neuron scan, T=8. x: [B=32,T=8,S=131072] fp32. Pure streaming.
//
// Experiment R4: two float4 sites per thread, all 16 timestep loads
// front-batched (per-thread MLP=16) to test latency- vs ceiling-bound
// hypothesis for the ~5.8 TB/s plateau.
//
// Site A = linear id i, site B = i + total4/2 (second half of the tensor),
// so warp-level coalescing is preserved for both streams.

#define VTH 0.5f
#define S4C 32768u      // spatial float4 per (b,t)
#define S4_SHIFT 15
#define S4_MASK 32767

#define SCAN_LANE(m_, xv_, r_)                    \
    m_ = fmaf(tau, m_, xv_);                      \
    r_ = (m_ > VTH) ? 1.0f : 0.0f;                \
    m_ = (m_ > VTH) ? 0.0f : m_;

__global__ __launch_bounds__(128) void plif_kernel(
    const float4* __restrict__ x,
    const float* __restrict__ w,
    float4* __restrict__ out)
{
    // 4096 blocks x 128 threads = 524288 threads; each owns 2 sites.
    unsigned i = blockIdx.x * 128u + threadIdx.x;        // site A: 0..524287
    unsigned j = i + 524288u;                            // site B: second half

    float wv = __ldg(w);
    float tau = 1.0f / (1.0f + __expf(-wv));

    unsigned ba = ((i >> S4_SHIFT) << 3) * S4C + (i & S4_MASK);
    unsigned bb = ((j >> S4_SHIFT) << 3) * S4C + (j & S4_MASK);

    const float4* pxa = x + ba;
    const float4* pxb = x + bb;
    float4* poa = out + ba;
    float4* pob = out + bb;

    // Front-batch ALL 16 loads (8 per site) -> per-thread MLP = 16.
    float4 xa[8], xb[8];
#pragma unroll
    for (int t = 0; t < 8; t++) xa[t] = __ldcs(pxa + t * S4C);
#pragma unroll
    for (int t = 0; t < 8; t++) xb[t] = __ldcs(pxb + t * S4C);

    // Scan site A, storing each spike immediately (frees xa regs as we go).
    float4 m = make_float4(0.f, 0.f, 0.f, 0.f);
#pragma unroll
    for (int t = 0; t < 8; t++) {
        float4 r;
        SCAN_LANE(m.x, xa[t].x, r.x)
        SCAN_LANE(m.y, xa[t].y, r.y)
        SCAN_LANE(m.z, xa[t].z, r.z)
        SCAN_LANE(m.w, xa[t].w, r.w)
        __stcs(poa + t * S4C, r);
    }

    // Scan site B.
    m = make_float4(0.f, 0.f, 0.f, 0.f);
#pragma unroll
    for (int t = 0; t < 8; t++) {
        float4 r;
        SCAN_LANE(m.x, xb[t].x, r.x)
        SCAN_LANE(m.y, xb[t].y, r.y)
        SCAN_LANE(m.z, xb[t].z, r.z)
        SCAN_LANE(m.w, xb[t].w, r.w)
        __stcs(pob + t * S4C, r);
    }
}

extern "C" void kernel_launch(void* const* d_in, const int* in_sizes, int n_in,
                              void* d_out, int out_size) {
    const float4* x = (const float4*)d_in[0];
    const float* w = (const float*)d_in[1];
    float4* o = (float4*)d_out;

    // 1,048,576 float4 sites / 2 per thread / 128 threads = 4096 blocks exact
    plif_kernel<<<4096, 128>>>(x, w, o);
}